// round 14
// baseline (speedup 1.0000x reference)
#include <cuda_runtime.h>
#include <cstdint>

// ---------------------------------------------------------------------------
// Fused LSTM, persistent-cluster design for GB300 (sm_103a).   Round 13.
//
//   B=512, T=1024, D=64, U=128.  out = h_T  [512,128] fp32.
//
// 64 clusters x 4 CTAs (256 CTAs), 256 threads/CTA, 2 CTAs PER SM.
// Rationale: R12's residual was the serial per-step tail (combine, gate
// math, cluster barrier) which same-CTA warps cannot hide. Two independent
// co-resident CTAs hide each other's tails.
// CTA rank r owns u-slice [32r,32r+32) of all 4 gates = 128 cols.
// 4-way K-split: group g4=tid>>6 owns h-kp [16g4,16g4+16), x-kp [8g4,8g4+8).
// Thread owns 2 cols; h-weights in REGISTERS (16 kp x 2 col x 2 par = 64 f).
// x-weights (32 KB) in SMEM. smem/CTA = 58 KB -> 2 CTAs/SM; launch_bounds
// (256,2) forces regs<=128. h exchanged to all 3 peers via st.shared::cluster;
// lockstep via barrier.cluster (R8-proven). h double-buffered; x single.
// h-weight staging aliased over pbuf+gbuf in 4 x 16KB chunks (init only).
// ---------------------------------------------------------------------------

namespace {
constexpr int kT = 1024;
constexpr int kD = 64;
constexpr int kU = 128;
constexpr int kR = 8;                 // batch rows per cluster
constexpr int kThreads = 256;
constexpr int kXKP = kD / 2;          // 32 x k-pairs
constexpr int kHKP = kU / 2;          // 64 h k-pairs
constexpr int kColsC = 128;           // per-CTA cols (4 gates x 32 u)

// smem floats
constexpr int kXwF   = kXKP * kColsC * 2;      // 8192 f (32 KB) x-weights
constexpr int kVxOff = kXwF;                   // x values: 512 f
constexpr int kHbOff = kVxOff + 512;           // h: 2 buffers x 1024 f
constexpr int kPbOff = kHbOff + 2048;          // pbuf: 3 slots x 1024 f
constexpr int kGbOff = kPbOff + 3072;          // gbuf: 1024 f
constexpr int kHwOff = kPbOff;                 // staging alias (4096 f)
constexpr int kSmemBytes = (kGbOff + 1024) * 4;   // 59392 B
static_assert(kGbOff + 1024 == kHwOff + 4096, "staging aliases pbuf+gbuf");
}  // namespace

typedef unsigned long long ull;

__device__ __forceinline__ ull pk2(float a, float b) {
    ull r;
    asm("mov.b64 %0, {%1, %2};" : "=l"(r) : "f"(a), "f"(b));
    return r;
}
__device__ __forceinline__ void upk2(ull v, float& a, float& b) {
    asm("mov.b64 {%0, %1}, %2;" : "=f"(a), "=f"(b) : "l"(v));
}
__device__ __forceinline__ void fma2(ull& d, ull a, ull b) {
    asm("fma.rn.f32x2 %0, %1, %2, %0;" : "+l"(d) : "l"(a), "l"(b));
}
__device__ __forceinline__ void add2(ull& d, ull a) {
    asm("add.rn.f32x2 %0, %0, %1;" : "+l"(d) : "l"(a));
}
__device__ __forceinline__ float rcpa(float x) {
    float r;
    asm("rcp.approx.f32 %0, %1;" : "=f"(r) : "f"(x));
    return r;
}
__device__ __forceinline__ float sigf(float x) {
    return rcpa(1.0f + __expf(-x));
}
__device__ __forceinline__ float tanh_acc(float x) {
    float e = __expf(-2.0f * fabsf(x));
    float r = (1.0f - e) * rcpa(1.0f + e);
    return copysignf(r, x);
}
__device__ __forceinline__ uint32_t smem_u32(const void* p) {
    uint32_t a;
    asm("{ .reg .u64 t; cvta.to.shared.u64 t, %1; cvt.u32.u64 %0, t; }"
        : "=r"(a) : "l"(p));
    return a;
}

__global__ void __cluster_dims__(4, 1, 1) __launch_bounds__(kThreads, 2)
lstm_fused_kernel(const float* __restrict__ x,
                  const float* __restrict__ Wf, const float* __restrict__ Uf, const float* __restrict__ bf,
                  const float* __restrict__ Wi, const float* __restrict__ Ui, const float* __restrict__ bi,
                  const float* __restrict__ Wc, const float* __restrict__ Uc, const float* __restrict__ bc,
                  const float* __restrict__ Wo, const float* __restrict__ Uo, const float* __restrict__ bo,
                  float* __restrict__ out) {
    extern __shared__ float smem[];
    float* xw   = smem;                        // [xkp][j][par]  (persistent)
    float* vx   = smem + kVxOff;               // [xkp][row][par] (single buf)
    float* hb0  = smem + kHbOff;               // [hkp][row][par] (double buf)
    float* hb1  = hb0 + 1024;
    ull*   pb2  = (ull*)(smem + kPbOff);       // 3 slots x [r][t64] ull
    float* gbuf = smem + kGbOff;               // [row][128]
    float* hwS  = smem + kHwOff;               // staging chunk (alias)

    const int tid = threadIdx.x;
    uint32_t rank;
    asm("mov.u32 %0, %%cluster_ctarank;" : "=r"(rank));
    const int cl = blockIdx.x >> 2;            // cluster id -> batch row group

    const int g4  = tid >> 6;                  // K-group 0..3
    const int t64 = tid & 63;                  // column-thread id in group
    const int j0  = 2 * t64;                   // this thread's cols j0, j0+1

    // ---- stage x-weights into SMEM -----------------------------------------
    // xw[(k>>1)*256 + j*2 + (k&1)] = W_gate[k][u], j = gate*32+u', u=rank*32+u'
    for (int e = tid; e < kD * kColsC; e += kThreads) {
        int k = e >> 7;                        // 0..63
        int j = e & 127;
        int g = j >> 5;
        int u = (int)rank * 32 + (j & 31);
        const float* src = (g == 0) ? Wf : (g == 1) ? Wi : (g == 2) ? Wc : Wo;
        xw[(k >> 1) * 256 + j * 2 + (k & 1)] = src[k * kU + u];
    }

    // ---- stage h-weights in 4 chunks (aliased scratch), copy to registers --
    ull wh0[16], wh1[16];
    {
        const ulonglong2* hwS2 = (const ulonglong2*)hwS;
        for (int c = 0; c < 4; ++c) {
            __syncthreads();
            for (int e = tid; e < 32 * kColsC; e += kThreads) {
                int hkl = e >> 7;              // 0..31 local hk
                int j   = e & 127;
                int g   = j >> 5;
                int u   = (int)rank * 32 + (j & 31);
                int hk  = 32 * c + hkl;
                const float* src = (g == 0) ? Uf : (g == 1) ? Ui : (g == 2) ? Uc : Uo;
                hwS[(hkl >> 1) * 256 + j * 2 + (hkl & 1)] = src[hk * kU + u];
            }
            __syncthreads();
            if (g4 == c) {
#pragma unroll
                for (int i = 0; i < 16; ++i) {
                    ulonglong2 w = hwS2[i * 64 + t64];
                    wh0[i] = w.x;
                    wh1[i] = w.y;
                }
            }
        }
    }
    __syncthreads();                           // staging dead; pbuf/gbuf live

    // ---- per-thread bias (group0 applies in combine) ------------------------
    const int bg = j0 >> 5;
    const int bu = (int)rank * 32 + (j0 & 31);
    const float* bsrc = (bg == 0) ? bf : (bg == 1) ? bi : (bg == 2) ? bc : bo;
    const ull biasp = pk2(bsrc[bu], bsrc[bu + 1]);

    // x prefetch/stash mapping (threads 128..255): thread -> (row, dgrp)
    const int xtid = tid - 128;                // valid when tid >= 128
    const int xrow = xtid & 7;
    const int xdg  = xtid >> 3;                // 0..15
    const float4* xbase =
        (const float4*)(x + ((size_t)(cl * kR + xrow) * kT) * kD) + xdg;

    // gate-math mapping: 256 threads -> 1 (row, u') each
    const int gup  = tid & 31;
    const int grow = tid >> 5;                 // 0..7
    const int gu   = (int)rank * 32 + gup;
    const int hoff = (gu >> 1) * 16 + grow * 2 + (gu & 1);

    // peer CTA hb0 addresses (3 peers)
    uint32_t peer_hb0[3];
    {
        uint32_t my_hb0 = smem_u32(hb0);
#pragma unroll
        for (int p = 0; p < 3; ++p) {
            uint32_t prank = (rank + 1u + p) & 3u;
            asm("mapa.shared::cluster.u32 %0, %1, %2;"
                : "=r"(peer_hb0[p]) : "r"(my_hb0), "r"(prank));
        }
    }

    // ---- init: h_0 = 0 (own buffer), stash x_0 ------------------------------
    for (int i = tid; i < 1024; i += kThreads) hb0[i] = 0.0f;
    if (tid >= 128) {
        float4 x0 = __ldg(xbase);
        *(float2*)&vx[(2 * xdg + 0) * 16 + xrow * 2] = make_float2(x0.x, x0.y);
        *(float2*)&vx[(2 * xdg + 1) * 16 + xrow * 2] = make_float2(x0.z, x0.w);
    }
    float creg = 0.0f;
    __syncthreads();
    asm volatile("barrier.cluster.arrive.aligned;" ::: "memory");
    asm volatile("barrier.cluster.wait.aligned;"   ::: "memory");

    const ulonglong2* xw2 = (const ulonglong2*)xw;
    const ulonglong2* vx2 = (const ulonglong2*)vx;

    int cur = 0;
    for (int t = 0; t < kT; ++t) {
        // prefetch x_{t+1} (threads 128..255; DRAM hidden behind GEMV)
        float4 xn = make_float4(0, 0, 0, 0);
        if (tid >= 128 && t + 1 < kT) xn = __ldg(xbase + (size_t)(t + 1) * 16);

        const ulonglong2* hv2 = (const ulonglong2*)(cur ? hb1 : hb0);

        ull a0[8], a1[8];
#pragma unroll
        for (int r = 0; r < 8; ++r) { a0[r] = 0ull; a1[r] = 0ull; }

        // ---- h-part GEMV: weights from registers (16 kp) -------------------
#pragma unroll
        for (int i = 0; i < 16; ++i) {
            const ulonglong2* vp = hv2 + (g4 * 16 + i) * 4;
            ulonglong2 vA = vp[0];             // rows 0,1 (ke,ko each)
            ulonglong2 vB = vp[1];             // rows 2,3
            ulonglong2 vC = vp[2];             // rows 4,5
            ulonglong2 vD = vp[3];             // rows 6,7
            fma2(a0[0], vA.x, wh0[i]); fma2(a0[1], vA.y, wh0[i]);
            fma2(a0[2], vB.x, wh0[i]); fma2(a0[3], vB.y, wh0[i]);
            fma2(a0[4], vC.x, wh0[i]); fma2(a0[5], vC.y, wh0[i]);
            fma2(a0[6], vD.x, wh0[i]); fma2(a0[7], vD.y, wh0[i]);
            fma2(a1[0], vA.x, wh1[i]); fma2(a1[1], vA.y, wh1[i]);
            fma2(a1[2], vB.x, wh1[i]); fma2(a1[3], vB.y, wh1[i]);
            fma2(a1[4], vC.x, wh1[i]); fma2(a1[5], vC.y, wh1[i]);
            fma2(a1[6], vD.x, wh1[i]); fma2(a1[7], vD.y, wh1[i]);
        }
        // ---- x-part GEMV: weights from SMEM (8 kp) -------------------------
#pragma unroll
        for (int i = 0; i < 8; ++i) {
            int kp = g4 * 8 + i;
            ulonglong2 w = xw2[kp * 64 + t64]; // (ke,ko)@j0, (ke,ko)@j1
            const ulonglong2* vp = vx2 + kp * 4;
            ulonglong2 vA = vp[0];
            ulonglong2 vB = vp[1];
            ulonglong2 vC = vp[2];
            ulonglong2 vD = vp[3];
            fma2(a0[0], vA.x, w.x); fma2(a0[1], vA.y, w.x);
            fma2(a0[2], vB.x, w.x); fma2(a0[3], vB.y, w.x);
            fma2(a0[4], vC.x, w.x); fma2(a0[5], vC.y, w.x);
            fma2(a0[6], vD.x, w.x); fma2(a0[7], vD.y, w.x);
            fma2(a1[0], vA.x, w.y); fma2(a1[1], vA.y, w.y);
            fma2(a1[2], vB.x, w.y); fma2(a1[3], vB.y, w.y);
            fma2(a1[4], vC.x, w.y); fma2(a1[5], vC.y, w.y);
            fma2(a1[6], vD.x, w.y); fma2(a1[7], vD.y, w.y);
        }

        // lane-sum -> gfp[r] = (sum@j0, sum@j1)
        ull gfp[8];
#pragma unroll
        for (int r = 0; r < 8; ++r) {
            float s0lo, s0hi, s1lo, s1hi;
            upk2(a0[r], s0lo, s0hi);
            upk2(a1[r], s1lo, s1hi);
            gfp[r] = pk2(s0lo + s0hi, s1lo + s1hi);
        }
        if (g4 != 0) {
#pragma unroll
            for (int r = 0; r < 8; ++r)
                pb2[(g4 - 1) * 512 + r * 64 + t64] = gfp[r];
        }
        __syncthreads();                       // pbuf ready; h/x reads done

        if (g4 == 0) {
            // combine + bias, scatter to gbuf
#pragma unroll
            for (int r = 0; r < 8; ++r) {
                add2(gfp[r], pb2[0 * 512 + r * 64 + t64]);
                add2(gfp[r], pb2[1 * 512 + r * 64 + t64]);
                add2(gfp[r], pb2[2 * 512 + r * 64 + t64]);
                add2(gfp[r], biasp);
                *(ull*)&gbuf[r * kColsC + j0] = gfp[r];
            }
        } else if (tid >= 128 && t + 1 < kT) {
            // stash x_{t+1} (x reads completed at the sync above)
            *(float2*)&vx[(2 * xdg + 0) * 16 + xrow * 2] = make_float2(xn.x, xn.y);
            *(float2*)&vx[(2 * xdg + 1) * 16 + xrow * 2] = make_float2(xn.z, xn.w);
        }
        __syncthreads();                       // gbuf ready

        // ---- gate math: 1 (row,u') per thread ------------------------------
        {
            const float* gb = gbuf + grow * kColsC + gup;
            float f  = sigf(gb[0]);
            float ii = sigf(gb[32]);
            float cd = tanh_acc(gb[64]);
            float o  = sigf(gb[96]);
            float c  = f * creg + ii * cd;
            creg = c;
            float h  = o * tanh_acc(c);
            if (t < kT - 1) {
                float* hbn = cur ? hb0 : hb1;  // write NEXT buffer
                hbn[hoff] = h;                 // own copy
                uint32_t boff = (cur ? 0u : 4096u) + (uint32_t)(hoff * 4);
                uint32_t hbits = __float_as_uint(h);
#pragma unroll
                for (int p = 0; p < 3; ++p)    // 3 peer copies
                    asm volatile("st.shared::cluster.b32 [%0], %1;"
                                 :: "r"(peer_hb0[p] + boff), "r"(hbits)
                                 : "memory");
            } else {
                out[(size_t)(cl * kR + grow) * kU + gu] = h;
            }
        }

        // cluster barrier: lockstep + release DSMEM h stores (proven pattern)
        asm volatile("barrier.cluster.arrive.aligned;" ::: "memory");
        asm volatile("barrier.cluster.wait.aligned;"   ::: "memory");
        cur ^= 1;
    }
}

extern "C" void kernel_launch(void* const* d_in, const int* in_sizes, int n_in,
                              void* d_out, int out_size) {
    (void)in_sizes; (void)n_in; (void)out_size;
    const float* x  = (const float*)d_in[0];
    const float* Wf = (const float*)d_in[1];
    const float* Uf = (const float*)d_in[2];
    const float* bf = (const float*)d_in[3];
    const float* Wi = (const float*)d_in[4];
    const float* Ui = (const float*)d_in[5];
    const float* bi = (const float*)d_in[6];
    const float* Wc = (const float*)d_in[7];
    const float* Uc = (const float*)d_in[8];
    const float* bc = (const float*)d_in[9];
    const float* Wo = (const float*)d_in[10];
    const float* Uo = (const float*)d_in[11];
    const float* bo = (const float*)d_in[12];
    float* out = (float*)d_out;

    cudaFuncSetAttribute(lstm_fused_kernel,
                         cudaFuncAttributeMaxDynamicSharedMemorySize, kSmemBytes);
    const int grid = 64 * 4;   // 64 clusters x 4 CTAs = 256 CTAs (2/SM)
    lstm_fused_kernel<<<grid, kThreads, kSmemBytes>>>(
        x, Wf, Uf, bf, Wi, Ui, bi, Wc, Uc, bc, Wo, Uo, bo, out);
}

// round 17
// speedup vs baseline: 1.0844x; 1.0844x over previous
#include <cuda_runtime.h>
#include <cstdint>

// ---------------------------------------------------------------------------
// Fused LSTM, persistent-cluster design for GB300 (sm_103a).   Round 14.
//
//   B=512, T=1024, D=64, U=128.  out = h_T  [512,128] fp32.
//
// Base = R12 (best, 3361us): 64 clusters x 2 CTAs, 384 threads/CTA,
// h-weights in registers (3-way K-split 22/21/21), x-weights in SMEM.
// R14 tail cuts:
//  1) no gbuf phase: ALL groups publish partials (3 pbuf slots); after one
//     sync each thread combines its own gate columns straight from pbuf.
//  2) gate math on all 384 threads (512 (row,u') tasks; tid<128 take 2).
//  3) cluster barrier SPLIT: arrive right after h stores; the x-part GEMV
//     for step t+1 (+ x stash) runs between arrive and wait, hiding the
//     ~490cyc cluster-barrier latency under real FMA work.
// Sync skeleton stays proven-safe: syncthreads + barrier.cluster only,
// executed unconditionally by every thread.
// ---------------------------------------------------------------------------

namespace {
constexpr int kT = 1024;
constexpr int kD = 64;
constexpr int kU = 128;
constexpr int kR = 8;                 // batch rows per cluster
constexpr int kThreads = 384;
constexpr int kXKP = kD / 2;          // 32 x k-pairs
constexpr int kHKP = kU / 2;          // 64 h k-pairs
constexpr int kCols = 256;            // per-CTA output columns

// smem floats
constexpr int kXwF   = kXKP * kCols * 2;          // 16384 (64 KB) x-weights
constexpr int kVxOff = kXwF;                      // x values: 512 f
constexpr int kHbOff = kVxOff + kXKP * 16;        // h: 2 buffers x 1024 f
constexpr int kPbOff = kHbOff + 2 * kHKP * 16;    // pbuf: 3 slots x 2048 f
constexpr int kHwOff = kPbOff;                    // TEMP h-weights ALIASED
constexpr int kHwF   = kHKP * kCols * 2;          // 32768 f (dominates)
constexpr int kSmemBytes = (kHwOff + kHwF) * 4;   // 206848 B
static_assert(3 * 2048 <= kHwF, "pbuf fits inside staging alias");
}  // namespace

typedef unsigned long long ull;

__device__ __forceinline__ ull pk2(float a, float b) {
    ull r;
    asm("mov.b64 %0, {%1, %2};" : "=l"(r) : "f"(a), "f"(b));
    return r;
}
__device__ __forceinline__ void upk2(ull v, float& a, float& b) {
    asm("mov.b64 {%0, %1}, %2;" : "=f"(a), "=f"(b) : "l"(v));
}
__device__ __forceinline__ void fma2(ull& d, ull a, ull b) {
    asm("fma.rn.f32x2 %0, %1, %2, %0;" : "+l"(d) : "l"(a), "l"(b));
}
__device__ __forceinline__ float rcpa(float x) {
    float r;
    asm("rcp.approx.f32 %0, %1;" : "=f"(r) : "f"(x));
    return r;
}
__device__ __forceinline__ float sigf(float x) {
    return rcpa(1.0f + __expf(-x));
}
__device__ __forceinline__ float tanh_acc(float x) {
    float e = __expf(-2.0f * fabsf(x));
    float r = (1.0f - e) * rcpa(1.0f + e);
    return copysignf(r, x);
}
__device__ __forceinline__ uint32_t smem_u32(const void* p) {
    uint32_t a;
    asm("{ .reg .u64 t; cvta.to.shared.u64 t, %1; cvt.u32.u64 %0, t; }"
        : "=r"(a) : "l"(p));
    return a;
}

// h-GEMV: weights from registers (fully unrolled, compile-time trip count)
template <int HN>
__device__ __forceinline__ void gemv_h(const ulonglong2* __restrict__ hv2,
                                       int hk0, const ull* wh0, const ull* wh1,
                                       ull a0[8], ull a1[8]) {
#pragma unroll
    for (int i = 0; i < HN; ++i) {
        const ulonglong2* vp = hv2 + (hk0 + i) * 4;
        ulonglong2 vA = vp[0];     // rows 0,1
        ulonglong2 vB = vp[1];     // rows 2,3
        ulonglong2 vC = vp[2];     // rows 4,5
        ulonglong2 vD = vp[3];     // rows 6,7
        fma2(a0[0], vA.x, wh0[i]); fma2(a0[1], vA.y, wh0[i]);
        fma2(a0[2], vB.x, wh0[i]); fma2(a0[3], vB.y, wh0[i]);
        fma2(a0[4], vC.x, wh0[i]); fma2(a0[5], vC.y, wh0[i]);
        fma2(a0[6], vD.x, wh0[i]); fma2(a0[7], vD.y, wh0[i]);
        fma2(a1[0], vA.x, wh1[i]); fma2(a1[1], vA.y, wh1[i]);
        fma2(a1[2], vB.x, wh1[i]); fma2(a1[3], vB.y, wh1[i]);
        fma2(a1[4], vC.x, wh1[i]); fma2(a1[5], vC.y, wh1[i]);
        fma2(a1[6], vD.x, wh1[i]); fma2(a1[7], vD.y, wh1[i]);
    }
}

// x-GEMV: weights from SMEM
template <int XN>
__device__ __forceinline__ void gemv_x(const ulonglong2* __restrict__ xw2,
                                       const ulonglong2* __restrict__ vx2,
                                       int xk0, int tidw,
                                       ull a0[8], ull a1[8]) {
#pragma unroll
    for (int i = 0; i < XN; ++i) {
        int kp = xk0 + i;
        ulonglong2 w = xw2[kp * 128 + tidw];
        const ulonglong2* vp = vx2 + kp * 4;
        ulonglong2 vA = vp[0];
        ulonglong2 vB = vp[1];
        ulonglong2 vC = vp[2];
        ulonglong2 vD = vp[3];
        fma2(a0[0], vA.x, w.x); fma2(a0[1], vA.y, w.x);
        fma2(a0[2], vB.x, w.x); fma2(a0[3], vB.y, w.x);
        fma2(a0[4], vC.x, w.x); fma2(a0[5], vC.y, w.x);
        fma2(a0[6], vD.x, w.x); fma2(a0[7], vD.y, w.x);
        fma2(a1[0], vA.x, w.y); fma2(a1[1], vA.y, w.y);
        fma2(a1[2], vB.x, w.y); fma2(a1[3], vB.y, w.y);
        fma2(a1[4], vC.x, w.y); fma2(a1[5], vC.y, w.y);
        fma2(a1[6], vD.x, w.y); fma2(a1[7], vD.y, w.y);
    }
}

__global__ void __cluster_dims__(2, 1, 1) __launch_bounds__(kThreads, 1)
lstm_fused_kernel(const float* __restrict__ x,
                  const float* __restrict__ Wf, const float* __restrict__ Uf, const float* __restrict__ bf,
                  const float* __restrict__ Wi, const float* __restrict__ Ui, const float* __restrict__ bi,
                  const float* __restrict__ Wc, const float* __restrict__ Uc, const float* __restrict__ bc,
                  const float* __restrict__ Wo, const float* __restrict__ Uo, const float* __restrict__ bo,
                  float* __restrict__ out) {
    extern __shared__ float smem[];
    float* xw    = smem;                       // [xkp][j][par]  (persistent)
    float* vx    = smem + kVxOff;              // [xkp][row][par] (single buf)
    float* hb0   = smem + kHbOff;              // [hkp][row][par] (double buf)
    float* hb1   = hb0 + kHKP * 16;
    ull*   pb2   = (ull*)(smem + kPbOff);      // 3 slots x [r][tidw] ull
    float* pbufF = smem + kPbOff;              // float view: [s*2048+r*256+j]
    float* hwt   = smem + kHwOff;              // TEMP staged h-weights (alias)

    const int tid = threadIdx.x;
    uint32_t rank;
    asm("mov.u32 %0, %%cluster_ctarank;" : "=r"(rank));
    const int cl = blockIdx.x >> 1;

    const int g3   = tid >> 7;                 // K-group 0/1/2
    const int tidw = tid & 127;

    // per-group kp ranges: h 22/21/21, x 10/11/11
    const int hk0 = (g3 == 0) ? 0 : (1 + 21 * g3);     // 0, 22, 43
    const int hn  = (g3 == 0) ? 22 : 21;
    const int xk0 = (g3 == 0) ? 0 : (11 * g3 - 1);     // 0, 10, 21

    // x prefetch/stash mapping (group1): thread -> (row, 4-float d-group)
    const int xrow = tidw & 7;
    const int xdg  = tidw >> 3;                // 0..15
    const float4* xbase =
        (const float4*)(x + ((size_t)(cl * kR + xrow) * kT) * kD) + xdg;

    // ---- stage weights: x -> persistent xw, h -> temp hwt -------------------
    for (int idx = tid; idx < 192 * kCols; idx += kThreads) {
        int k = idx >> 8;                      // 0..191
        int j = idx & 255;
        int g = j >> 6;
        int u = (int)rank * 64 + (j & 63);
        if (k < kD) {
            const float* src = (g == 0) ? Wf : (g == 1) ? Wi : (g == 2) ? Wc : Wo;
            xw[(k >> 1) * 512 + j * 2 + (k & 1)] = src[k * kU + u];
        } else {
            int hk = k - kD;
            const float* src = (g == 0) ? Uf : (g == 1) ? Ui : (g == 2) ? Uc : Uo;
            hwt[(hk >> 1) * 512 + j * 2 + (hk & 1)] = src[hk * kU + u];
        }
    }
    __syncthreads();

    // ---- copy this thread's h-weight slice into registers -------------------
    ull wh0[22], wh1[22];
    {
        const ulonglong2* hw2 = (const ulonglong2*)hwt;
        for (int i = 0; i < hn; ++i) {
            ulonglong2 w = hw2[(hk0 + i) * 128 + tidw];
            wh0[i] = w.x;
            wh1[i] = w.y;
        }
        if (hn < 22) { wh0[21] = 0ull; wh1[21] = 0ull; }
    }
    __syncthreads();                           // hwt dead; pbuf live now

    // ---- gate-task mapping --------------------------------------------------
    // task1 (all threads): u' = tid&63, row = tid>>6 (0..5)
    // task2 (tid<128):     u' = tid&63, row = 6 + (tid>>6) (6..7)
    const int gup  = tid & 63;
    const int gu   = (int)rank * 64 + gup;
    const int row1 = tid >> 6;
    const int row2 = 6 + (tid >> 6);           // valid for tid < 128
    // per-u bias for the 4 gates (shared by both tasks)
    const float b4f = bf[gu], b4i = bi[gu], b4c = bc[gu], b4o = bo[gu];

    // peer CTA's hb0 shared-address (cluster DSMEM)
    uint32_t peer_hb0;
    {
        uint32_t prank = rank ^ 1u;
        uint32_t my_hb0 = smem_u32(hb0);
        asm("mapa.shared::cluster.u32 %0, %1, %2;"
            : "=r"(peer_hb0) : "r"(my_hb0), "r"(prank));
    }

    // ---- init: h_0 = 0, stash x_0 -------------------------------------------
    for (int i = tid; i < kHKP * 16; i += kThreads) hb0[i] = 0.0f;
    if (g3 == 1) {
        float4 x0 = __ldg(xbase);
        *(float2*)&vx[(2 * xdg + 0) * 16 + xrow * 2] = make_float2(x0.x, x0.y);
        *(float2*)&vx[(2 * xdg + 1) * 16 + xrow * 2] = make_float2(x0.z, x0.w);
    }
    float creg1 = 0.0f, creg2 = 0.0f;
    __syncthreads();

    const ulonglong2* xw2 = (const ulonglong2*)xw;
    const ulonglong2* vx2 = (const ulonglong2*)vx;

    // accumulators carry the x(t) contribution into iteration t
    ull a0[8], a1[8];
#pragma unroll
    for (int r = 0; r < 8; ++r) { a0[r] = 0ull; a1[r] = 0ull; }

    // prologue: x-GEMV for step 0, then stash x_1
    {
        if (g3 == 0) gemv_x<10>(xw2, vx2, xk0, tidw, a0, a1);
        else         gemv_x<11>(xw2, vx2, xk0, tidw, a0, a1);
        __syncthreads();                       // x_0 reads done
        if (g3 == 1) {
            float4 x1 = __ldg(xbase + 16);
            *(float2*)&vx[(2 * xdg + 0) * 16 + xrow * 2] = make_float2(x1.x, x1.y);
            *(float2*)&vx[(2 * xdg + 1) * 16 + xrow * 2] = make_float2(x1.z, x1.w);
        }
        __syncthreads();
    }
    asm volatile("barrier.cluster.arrive.aligned;" ::: "memory");
    asm volatile("barrier.cluster.wait.aligned;"   ::: "memory");

    int cur = 0;
    for (int t = 0; t < kT; ++t) {
        // issue prefetch of x_{t+2} early (consumed at the stash below)
        float4 xn = make_float4(0, 0, 0, 0);
        if (g3 == 1 && t + 2 < kT) xn = __ldg(xbase + (size_t)(t + 2) * 16);

        // ---- h-part GEMV (adds onto carried x(t) partials) -----------------
        const ulonglong2* hv2 = (const ulonglong2*)(cur ? hb1 : hb0);
        if (g3 == 0) gemv_h<22>(hv2, hk0, wh0, wh1, a0, a1);
        else         gemv_h<21>(hv2, hk0, wh0, wh1, a0, a1);

        // lane-sum + publish (ALL groups -> 3 pbuf slots); reset accumulators
#pragma unroll
        for (int r = 0; r < 8; ++r) {
            float s0lo, s0hi, s1lo, s1hi;
            upk2(a0[r], s0lo, s0hi);
            upk2(a1[r], s1lo, s1hi);
            pb2[g3 * 1024 + r * 128 + tidw] = pk2(s0lo + s0hi, s1lo + s1hi);
            a0[r] = 0ull; a1[r] = 0ull;
        }
        __syncthreads();                       // pbuf ready; h/x reads done

        // ---- gate math: combine from pbuf + bias, 1-2 tasks per thread -----
        float* hbn = cur ? hb0 : hb1;          // NEXT h buffer
        const uint32_t pbase = peer_hb0 + (cur ? 0u : 4096u);
        const bool last = (t == kT - 1);
        {
            const float* p0 = pbufF + row1 * 256 + gup;
            float gf = p0[0]    + p0[2048]      + p0[4096]      + b4f;
            float gi = p0[64]   + p0[2048+64]   + p0[4096+64]   + b4i;
            float gc = p0[128]  + p0[2048+128]  + p0[4096+128]  + b4c;
            float go = p0[192]  + p0[2048+192]  + p0[4096+192]  + b4o;
            float f  = sigf(gf), ii = sigf(gi);
            float cd = tanh_acc(gc), o = sigf(go);
            float c  = f * creg1 + ii * cd;
            creg1 = c;
            float h  = o * tanh_acc(c);
            if (!last) {
                int off = (gu >> 1) * 16 + row1 * 2 + (gu & 1);
                hbn[off] = h;
                asm volatile("st.shared::cluster.b32 [%0], %1;"
                             :: "r"(pbase + (uint32_t)(off * 4)),
                                "r"(__float_as_uint(h)) : "memory");
            } else {
                out[(size_t)(cl * kR + row1) * kU + gu] = h;
            }
        }
        if (tid < 128) {
            const float* p0 = pbufF + row2 * 256 + gup;
            float gf = p0[0]    + p0[2048]      + p0[4096]      + b4f;
            float gi = p0[64]   + p0[2048+64]   + p0[4096+64]   + b4i;
            float gc = p0[128]  + p0[2048+128]  + p0[4096+128]  + b4c;
            float go = p0[192]  + p0[2048+192]  + p0[4096+192]  + b4o;
            float f  = sigf(gf), ii = sigf(gi);
            float cd = tanh_acc(gc), o = sigf(go);
            float c  = f * creg2 + ii * cd;
            creg2 = c;
            float h  = o * tanh_acc(c);
            if (!last) {
                int off = (gu >> 1) * 16 + row2 * 2 + (gu & 1);
                hbn[off] = h;
                asm volatile("st.shared::cluster.b32 [%0], %1;"
                             :: "r"(pbase + (uint32_t)(off * 4)),
                                "r"(__float_as_uint(h)) : "memory");
            } else {
                out[(size_t)(cl * kR + row2) * kU + gu] = h;
            }
        }

        // ---- barrier SPLIT: arrive now, hide wait under x-GEMV(t+1) --------
        asm volatile("barrier.cluster.arrive.aligned;" ::: "memory");

        if (t + 1 < kT) {
            if (g3 == 0) gemv_x<10>(xw2, vx2, xk0, tidw, a0, a1);
            else         gemv_x<11>(xw2, vx2, xk0, tidw, a0, a1);
        }
        __syncthreads();                       // pbuf + vx reads done
        if (g3 == 1 && t + 2 < kT) {           // stash x_{t+2}
            *(float2*)&vx[(2 * xdg + 0) * 16 + xrow * 2] = make_float2(xn.x, xn.y);
            *(float2*)&vx[(2 * xdg + 1) * 16 + xrow * 2] = make_float2(xn.z, xn.w);
        }

        asm volatile("barrier.cluster.wait.aligned;"   ::: "memory");
        cur ^= 1;
    }
}

extern "C" void kernel_launch(void* const* d_in, const int* in_sizes, int n_in,
                              void* d_out, int out_size) {
    (void)in_sizes; (void)n_in; (void)out_size;
    const float* x  = (const float*)d_in[0];
    const float* Wf = (const float*)d_in[1];
    const float* Uf = (const float*)d_in[2];
    const float* bf = (const float*)d_in[3];
    const float* Wi = (const float*)d_in[4];
    const float* Ui = (const float*)d_in[5];
    const float* bi = (const float*)d_in[6];
    const float* Wc = (const float*)d_in[7];
    const float* Uc = (const float*)d_in[8];
    const float* bc = (const float*)d_in[9];
    const float* Wo = (const float*)d_in[10];
    const float* Uo = (const float*)d_in[11];
    const float* bo = (const float*)d_in[12];
    float* out = (float*)d_out;

    cudaFuncSetAttribute(lstm_fused_kernel,
                         cudaFuncAttributeMaxDynamicSharedMemorySize, kSmemBytes);
    const int grid = 64 * 2;   // 64 clusters x 2 CTAs
    lstm_fused_kernel<<<grid, kThreads, kSmemBytes>>>(
        x, Wf, Uf, bf, Wi, Ui, bi, Wc, Uc, bc, Wo, Uo, bo, out);
}